// round 14
// baseline (speedup 1.0000x reference)
#include <cuda_runtime.h>
#include <cuda_fp16.h>
#include <cstdint>

// Problem constants
#define Bdim   8
#define Cdim   64
#define Ndim   40962
#define Kn     7
#define KN     (Kn * Ndim)
#define OUTd   64
#define TN     128                    // n-tile per CTA
#define NTILES ((Ndim + TN - 1) / TN) // 321

// Smem: four 16KB chunk buffers (128 rows x 128B, XOR-swizzled 16B slots) + idx
#define CHUNK_B    (TN * 128)         // 16384 bytes
#define NSTAGE     4
#define SMEM_BYTES (NSTAGE * CHUNK_B + TN * Kn * 4)   // 69,120 B -> 3 CTAs/SM

// Epilogue staging tile: 64 o-rows x 136-float stride (bank-conflict-free)
#define DS_STRIDE  136                // 64*136*4 = 34,816 B <= chunk region

// W fragment image: 4 mb-blocks x 28 ksteps x 32 lanes x 4 b32 (half2 pairs)
#define WP_U32    (4 * 28 * 32 * 4)   // 14336
#define WP_BLOCKS ((WP_U32 + 255) / 256)  // 56

// Combined prep grid ranges
#define NB32     ((Ndim + 31) / 32)   // 1281 transpose column-blocks per batch
#define TBLOCKS  (NB32 * Bdim)        // 10248
#define IBLOCKS  280

// Device scratch (allocation-free rule). 256B-aligned for cp.async/LDG.128.
__device__ __align__(256) __half   g_xh[(size_t)Bdim * Ndim * Cdim];
__device__ __align__(256) uint32_t g_wp[WP_U32];
__device__ __align__(256) int      g_idx[KN];

__device__ __forceinline__ uint32_t smem_u32(const void* p) {
    return (uint32_t)__cvta_generic_to_shared(p);
}
__device__ __forceinline__ void cp16(void* dst, const void* src) {
    asm volatile("cp.async.cg.shared.global [%0], [%1], 16;\n"
                 ::"r"(smem_u32(dst)), "l"(src));
}
#define CP_COMMIT() asm volatile("cp.async.commit_group;\n")

// ---------------------------------------------------------------------------
// Kernel 0: combined prep (transpose + W pack + idx normalize), one launch.
//  blocks [0, TBLOCKS): transpose x [B,C,N] -> g_xh [B,N,C] fp16
//  blocks [TBLOCKS, +WP_BLOCKS): pack W into fp16 A-fragment stream
//  blocks [TBLOCKS+WP_BLOCKS, +IBLOCKS): normalize neigh (int32 OR int64)
// ---------------------------------------------------------------------------
__global__ void prep_kernel(const float* __restrict__ x,
                            const void* __restrict__ neigh,
                            const float* __restrict__ W) {
    int tid = threadIdx.x;

    if (blockIdx.x < TBLOCKS) {
        // ---- transpose: 32 n x 64 c tile, smem round trip ----
        __shared__ float tile[64][33];
        int b  = blockIdx.x / NB32;
        int n0 = (blockIdx.x % NB32) * 32;
        const float* xb = x + (size_t)b * Cdim * Ndim;

        int nl = tid & 31, cb = tid >> 5;   // load: n = n0+nl, c = cb*8 + r
#pragma unroll
        for (int r = 0; r < 8; r++) {
            int c = cb * 8 + r;
            int n = n0 + nl;
            tile[c][nl] = (n < Ndim) ? xb[(size_t)c * Ndim + n] : 0.f;
        }
        __syncthreads();
        int c2 = tid & 31, nb = tid >> 5;   // store: half2 col c2
        __half2* xhb = (__half2*)(g_xh + (size_t)b * Ndim * Cdim);
#pragma unroll
        for (int r = 0; r < 4; r++) {
            int n = n0 + nb + r * 8;
            if (n < Ndim)
                xhb[(size_t)n * 32 + c2] =
                    __floats2half2_rn(tile[2 * c2][nb + r * 8],
                                      tile[2 * c2 + 1][nb + r * 8]);
        }
        return;
    }

    if (blockIdx.x < TBLOCKS + WP_BLOCKS) {
        // ---- W pack: b32 i = (((mb*28+ks)*32+lane)*4 + r) ----
        int i = (blockIdx.x - TBLOCKS) * 256 + tid;
        if (i >= WP_U32) return;
        int r  = i & 3;
        int l  = (i >> 2) & 31;
        int ks = (i >> 7) % 28;
        int mb = (i >> 7) / 28;        // 0..3
        int o  = mb * 16 + (l >> 2) + (r & 1) * 8;
        int kc = ks * 16 + 2 * (l & 3) + ((r >> 1) & 1) * 8;
        __half h0 = __float2half_rn(W[o * 448 + kc]);
        __half h1 = __float2half_rn(W[o * 448 + kc + 1]);
        g_wp[i] = (uint32_t)__half_as_ushort(h0) |
                  ((uint32_t)__half_as_ushort(h1) << 16);
        return;
    }

    // ---- idx normalize. Dtype detected per-block: int64 input has all-zero
    // odd int32 words in the first 4096; random int32 indices cannot. ----
    __shared__ int s_is64;
    const int* p32 = (const int*)neigh;
    unsigned acc = 0;
#pragma unroll
    for (int q = 0; q < 8; q++) acc |= (unsigned)p32[2 * (tid + 256 * q) + 1];
#pragma unroll
    for (int o = 16; o > 0; o >>= 1) acc |= __shfl_down_sync(~0u, acc, o);
    if (tid == 0) s_is64 = 1;
    __syncthreads();
    if ((tid & 31) == 0 && acc != 0) s_is64 = 0;
    __syncthreads();
    int is64 = s_is64;
    const long long* p64 = (const long long*)neigh;
    int bx = blockIdx.x - TBLOCKS - WP_BLOCKS;
    for (int i = bx * 256 + tid; i < KN; i += IBLOCKS * 256)
        g_idx[i] = is64 ? (int)p64[i] : p32[i];
}

// ---------------------------------------------------------------------------
// Kernel 1: fused gather + fp16 tensor-core GEMM, 4-stage pipeline,
// single barrier per chunk, 32o x 32n warp tiles, 3 CTAs/SM,
// smem-staged coalesced epilogue.
// ---------------------------------------------------------------------------
// Gather chunk k into smem: row n (128B = 64 halves), 16B slot j swizzled by
// (j ^ (n&7)) for conflict-free ldmatrix.
__device__ __forceinline__ void gather_chunk(const __half* __restrict__ xb,
                                             const int* __restrict__ idx_s,
                                             int k, char* __restrict__ buf,
                                             int tid) {
#pragma unroll
    for (int p = 0; p < 4; p++) {
        int e  = tid + 256 * p;   // 0..1023
        int nl = e >> 3;          // row 0..127
        int j  = e & 7;           // 16B slot
        int g  = idx_s[nl * Kn + k];
        const __half* src = xb + ((size_t)g << 6) + (j << 3);
        char* dst = buf + nl * 128 + ((j ^ (nl & 7)) << 4);
        cp16(dst, src);
    }
}

__device__ __forceinline__ void mma16(float* d, uint32_t a0, uint32_t a1,
                                      uint32_t a2, uint32_t a3, uint32_t b0,
                                      uint32_t b1) {
    asm volatile(
        "mma.sync.aligned.m16n8k16.row.col.f32.f16.f16.f32 "
        "{%0,%1,%2,%3}, {%4,%5,%6,%7}, {%8,%9}, {%0,%1,%2,%3};\n"
        : "+f"(d[0]), "+f"(d[1]), "+f"(d[2]), "+f"(d[3])
        : "r"(a0), "r"(a1), "r"(a2), "r"(a3), "r"(b0), "r"(b1));
}

// Compute one chunk (K=64 -> 4 ksteps of k16) for this warp.
// Warp tile: 32 output rows (mb pair 2*wm..) x 32 n-cols (quarter wn).
// A loaded per-h (4 live uint4) to stay under the 85-reg cap for 3 CTAs/SM.
__device__ __forceinline__ void compute_chunk(uint32_t bbase, int k, int wm,
                                              int wn, int lane,
                                              float d[2][4][4]) {
    int rr = lane & 7, gA = lane >> 3;
    const uint4* wp4 = (const uint4*)g_wp;
#pragma unroll
    for (int h = 0; h < 2; h++) {
        uint4 A[2][2];   // [mb][kq]
#pragma unroll
        for (int mb = 0; mb < 2; mb++)
#pragma unroll
            for (int kq = 0; kq < 2; kq++) {
                int ks = k * 4 + 2 * h + kq;
                A[mb][kq] =
                    __ldg(&wp4[((2 * wm + mb) * 28 + ks) * 32 + lane]);
            }
#pragma unroll
        for (int tt = 0; tt < 4; tt++) {
            uint32_t addr = bbase + (uint32_t)((wn * 32 + tt * 8 + rr) * 128) +
                            (uint32_t)(((4 * h + gA) ^ rr) << 4);
            uint32_t b0, b1, b2, b3;
            asm volatile(
                "ldmatrix.sync.aligned.m8n8.x4.shared.b16 {%0,%1,%2,%3}, [%4];"
                : "=r"(b0), "=r"(b1), "=r"(b2), "=r"(b3)
                : "r"(addr));
            mma16(d[0][tt], A[0][0].x, A[0][0].y, A[0][0].z, A[0][0].w, b0, b1);
            mma16(d[1][tt], A[1][0].x, A[1][0].y, A[1][0].z, A[1][0].w, b0, b1);
            mma16(d[0][tt], A[0][1].x, A[0][1].y, A[0][1].z, A[0][1].w, b2, b3);
            mma16(d[1][tt], A[1][1].x, A[1][1].y, A[1][1].z, A[1][1].w, b2, b3);
        }
    }
}

__global__ __launch_bounds__(256, 3) void fused_kernel(
    const float* __restrict__ bias, float* __restrict__ out) {
    extern __shared__ char sm[];
    int* idx_s = (int*)(sm + NSTAGE * CHUNK_B);

    int tid  = threadIdx.x;
    int lane = tid & 31;
    int w    = tid >> 5;
    int wm   = w & 1;   // M half (32 output rows)
    int wn   = w >> 1;  // N quarter (32 n-cols)
    int b    = blockIdx.y;
    int n0   = blockIdx.x * TN;
    const __half* xb = g_xh + (size_t)b * Ndim * Cdim;

    for (int e = tid; e < TN * Kn; e += 256) {
        int gi = n0 * Kn + e;
        idx_s[e] = (gi < KN) ? g_idx[gi] : 0;
    }
    __syncthreads();

    // Prologue: 3 chunks in flight.
    gather_chunk(xb, idx_s, 0, sm + 0 * CHUNK_B, tid); CP_COMMIT();
    gather_chunk(xb, idx_s, 1, sm + 1 * CHUNK_B, tid); CP_COMMIT();
    gather_chunk(xb, idx_s, 2, sm + 2 * CHUNK_B, tid); CP_COMMIT();

    float d[2][4][4];
#pragma unroll
    for (int i = 0; i < 2; i++)
#pragma unroll
        for (int j = 0; j < 4; j++)
#pragma unroll
            for (int q = 0; q < 4; q++) d[i][j][q] = 0.f;

    uint32_t bb = smem_u32(sm);

#pragma unroll
    for (int k = 0; k < Kn; k++) {
        // Chunk k must be complete; younger gathers may remain in flight.
        if (k < 5)       asm volatile("cp.async.wait_group 2;\n");
        else if (k == 5) asm volatile("cp.async.wait_group 1;\n");
        else             asm volatile("cp.async.wait_group 0;\n");
        // Barrier makes chunk k visible AND proves all warps finished chunk
        // k-1, so buffer (k+3)&3 == (k-1)&3 is free. One barrier per chunk.
        __syncthreads();
        if (k + 3 < Kn) {
            gather_chunk(xb, idx_s, k + 3, sm + ((k + 3) & 3) * CHUNK_B, tid);
            CP_COMMIT();
        }
        compute_chunk(bb + (uint32_t)((k & 3) * CHUNK_B), k, wm, wn, lane, d);
    }

    // ---- Staged epilogue: accumulators -> smem D tile -> coalesced STG ----
    __syncthreads();   // all warps done reading chunk buffers
    float* ds = (float*)sm;   // 64 rows x DS_STRIDE floats
#pragma unroll
    for (int mb2 = 0; mb2 < 2; mb2++) {
        int o = wm * 32 + mb2 * 16 + (lane >> 2);
#pragma unroll
        for (int tt = 0; tt < 4; tt++) {
            int nb = wn * 32 + tt * 8 + 2 * (lane & 3);
            *reinterpret_cast<float2*>(&ds[o * DS_STRIDE + nb]) =
                make_float2(d[mb2][tt][0], d[mb2][tt][1]);
            *reinterpret_cast<float2*>(&ds[(o + 8) * DS_STRIDE + nb]) =
                make_float2(d[mb2][tt][2], d[mb2][tt][3]);
        }
    }
    __syncthreads();
    // Warp w writes output rows [8w, 8w+8): contiguous 256B STG.64 bursts.
    // (float4 impossible: Ndim*4 % 16 == 8, odd rows are 8B-aligned only.)
#pragma unroll
    for (int r = 0; r < 8; r++) {
        int o = w * 8 + r;
        float bv = __ldg(&bias[o]);
        float* orow = out + ((size_t)(b * OUTd + o)) * Ndim + n0;
#pragma unroll
        for (int s = 0; s < 2; s++) {
            int nl = s * 64 + lane * 2;
            float2 v = *reinterpret_cast<float2*>(&ds[o * DS_STRIDE + nl]);
            v.x += bv;
            v.y += bv;
            int nb = n0 + nl;
            if (nb + 1 < Ndim)
                *reinterpret_cast<float2*>(orow + nl) = v;
            else if (nb < Ndim)
                orow[nl] = v.x;
        }
    }
}

// ---------------------------------------------------------------------------
// Launch
// ---------------------------------------------------------------------------
extern "C" void kernel_launch(void* const* d_in, const int* in_sizes, int n_in,
                              void* d_out, int out_size) {
    const float* x     = (const float*)d_in[0];
    const void*  neigh = d_in[1];   // int32 OR int64 (jax x64 trap)
    const float* W     = (const float*)d_in[2];
    const float* bias  = (const float*)d_in[3];
    float*       out   = (float*)d_out;

    cudaFuncSetAttribute(fused_kernel,
                         cudaFuncAttributeMaxDynamicSharedMemorySize,
                         SMEM_BYTES);

    prep_kernel<<<TBLOCKS + WP_BLOCKS + IBLOCKS, 256>>>(x, neigh, W);
    fused_kernel<<<dim3(NTILES, Bdim), 256, SMEM_BYTES>>>(bias, out);
}

// round 17
// speedup vs baseline: 1.3177x; 1.3177x over previous
#include <cuda_runtime.h>
#include <cuda_fp16.h>
#include <cstdint>

// Problem constants
#define Bdim   8
#define Cdim   64
#define Ndim   40962
#define Kn     7
#define KN     (Kn * Ndim)
#define OUTd   64
#define TN     128                    // n-tile per CTA
#define NTILES ((Ndim + TN - 1) / TN) // 321

// W fragment image: 4 mb-blocks x 28 ksteps x 32 lanes x 4 b32 (half2 pairs)
#define WP_U32    (4 * 28 * 32 * 4)   // 14336 u32 = 57,344 B
#define W_BYTES   (WP_U32 * 4)
#define WP_BLOCKS ((WP_U32 + 255) / 256)  // 56

// Smem: [W image][3 chunk buffers (128 rows x 128B, XOR-swizzled)][idx]
#define CHUNK_B    (TN * 128)         // 16384 bytes
#define NSTAGE     3
#define OFF_CH     W_BYTES                            // 57,344
#define OFF_IDX    (OFF_CH + NSTAGE * CHUNK_B)        // 106,496
#define SMEM_BYTES (OFF_IDX + TN * Kn * 4)            // 110,080 -> 2 CTAs/SM

// Combined prep grid ranges
#define NB32     ((Ndim + 31) / 32)   // 1281 transpose column-blocks per batch
#define TBLOCKS  (NB32 * Bdim)        // 10248
#define IBLOCKS  280

// Device scratch (allocation-free rule). 256B-aligned for cp.async/LDG.128.
__device__ __align__(256) __half   g_xh[(size_t)Bdim * Ndim * Cdim];
__device__ __align__(256) uint32_t g_wp[WP_U32];
__device__ __align__(256) int      g_idx[KN];

__device__ __forceinline__ uint32_t smem_u32(const void* p) {
    return (uint32_t)__cvta_generic_to_shared(p);
}
__device__ __forceinline__ void cp16(void* dst, const void* src) {
    asm volatile("cp.async.cg.shared.global [%0], [%1], 16;\n"
                 ::"r"(smem_u32(dst)), "l"(src));
}
#define CP_COMMIT() asm volatile("cp.async.commit_group;\n")

// ---------------------------------------------------------------------------
// Kernel 0: combined prep (transpose + W pack + idx normalize), one launch.
//  blocks [0, TBLOCKS): transpose x [B,C,N] -> g_xh [B,N,C] fp16
//  blocks [TBLOCKS, +WP_BLOCKS): pack W into fp16 A-fragment stream
//  blocks [TBLOCKS+WP_BLOCKS, +IBLOCKS): normalize neigh (int32 OR int64)
// ---------------------------------------------------------------------------
__global__ void prep_kernel(const float* __restrict__ x,
                            const void* __restrict__ neigh,
                            const float* __restrict__ W) {
    int tid = threadIdx.x;

    if (blockIdx.x < TBLOCKS) {
        // ---- transpose: 32 n x 64 c tile, smem round trip ----
        __shared__ float tile[64][33];
        int b  = blockIdx.x / NB32;
        int n0 = (blockIdx.x % NB32) * 32;
        const float* xb = x + (size_t)b * Cdim * Ndim;

        int nl = tid & 31, cb = tid >> 5;   // load: n = n0+nl, c = cb*8 + r
#pragma unroll
        for (int r = 0; r < 8; r++) {
            int c = cb * 8 + r;
            int n = n0 + nl;
            tile[c][nl] = (n < Ndim) ? xb[(size_t)c * Ndim + n] : 0.f;
        }
        __syncthreads();
        int c2 = tid & 31, nb = tid >> 5;   // store: half2 col c2
        __half2* xhb = (__half2*)(g_xh + (size_t)b * Ndim * Cdim);
#pragma unroll
        for (int r = 0; r < 4; r++) {
            int n = n0 + nb + r * 8;
            if (n < Ndim)
                xhb[(size_t)n * 32 + c2] =
                    __floats2half2_rn(tile[2 * c2][nb + r * 8],
                                      tile[2 * c2 + 1][nb + r * 8]);
        }
        return;
    }

    if (blockIdx.x < TBLOCKS + WP_BLOCKS) {
        // ---- W pack: b32 i = (((mb*28+ks)*32+lane)*4 + r) ----
        int i = (blockIdx.x - TBLOCKS) * 256 + tid;
        if (i >= WP_U32) return;
        int r  = i & 3;
        int l  = (i >> 2) & 31;
        int ks = (i >> 7) % 28;
        int mb = (i >> 7) / 28;        // 0..3
        int o  = mb * 16 + (l >> 2) + (r & 1) * 8;
        int kc = ks * 16 + 2 * (l & 3) + ((r >> 1) & 1) * 8;
        __half h0 = __float2half_rn(W[o * 448 + kc]);
        __half h1 = __float2half_rn(W[o * 448 + kc + 1]);
        g_wp[i] = (uint32_t)__half_as_ushort(h0) |
                  ((uint32_t)__half_as_ushort(h1) << 16);
        return;
    }

    // ---- idx normalize. Dtype detected per-block: int64 input has all-zero
    // odd int32 words in the first 4096; random int32 indices cannot. ----
    __shared__ int s_is64;
    const int* p32 = (const int*)neigh;
    unsigned acc = 0;
#pragma unroll
    for (int q = 0; q < 8; q++) acc |= (unsigned)p32[2 * (tid + 256 * q) + 1];
#pragma unroll
    for (int o = 16; o > 0; o >>= 1) acc |= __shfl_down_sync(~0u, acc, o);
    if (tid == 0) s_is64 = 1;
    __syncthreads();
    if ((tid & 31) == 0 && acc != 0) s_is64 = 0;
    __syncthreads();
    int is64 = s_is64;
    const long long* p64 = (const long long*)neigh;
    int bx = blockIdx.x - TBLOCKS - WP_BLOCKS;
    for (int i = bx * 256 + tid; i < KN; i += IBLOCKS * 256)
        g_idx[i] = is64 ? (int)p64[i] : p32[i];
}

// ---------------------------------------------------------------------------
// Kernel 1: fused gather + fp16 tensor-core GEMM.
// W image resident in smem (one cp.async copy per CTA); A-fragments via
// conflict-free LDS.128 (29 cyc) instead of L2-latency LDG. 3-stage chunk
// ring, single barrier per chunk, 32o x 32n warp tiles, 2 CTAs/SM.
// ---------------------------------------------------------------------------
// Gather chunk k into smem: row n (128B = 64 halves), 16B slot j swizzled by
// (j ^ (n&7)) for conflict-free ldmatrix.
__device__ __forceinline__ void gather_chunk(const __half* __restrict__ xb,
                                             const int* __restrict__ idx_s,
                                             int k, char* __restrict__ buf,
                                             int tid) {
#pragma unroll
    for (int p = 0; p < 4; p++) {
        int e  = tid + 256 * p;   // 0..1023
        int nl = e >> 3;          // row 0..127
        int j  = e & 7;           // 16B slot
        int g  = idx_s[nl * Kn + k];
        const __half* src = xb + ((size_t)g << 6) + (j << 3);
        char* dst = buf + nl * 128 + ((j ^ (nl & 7)) << 4);
        cp16(dst, src);
    }
}

__device__ __forceinline__ void mma16(float* d, uint32_t a0, uint32_t a1,
                                      uint32_t a2, uint32_t a3, uint32_t b0,
                                      uint32_t b1) {
    asm volatile(
        "mma.sync.aligned.m16n8k16.row.col.f32.f16.f16.f32 "
        "{%0,%1,%2,%3}, {%4,%5,%6,%7}, {%8,%9}, {%0,%1,%2,%3};\n"
        : "+f"(d[0]), "+f"(d[1]), "+f"(d[2]), "+f"(d[3])
        : "r"(a0), "r"(a1), "r"(a2), "r"(a3), "r"(b0), "r"(b1));
}

// Compute one chunk (K=64 -> 4 ksteps of k16) for this warp.
// Warp tile: 32 output rows (mb pair 2*wm..) x 32 n-cols (quarter wn).
// A fragments from resident smem W image: LDS.128, conflict-free
// (32 lanes x consecutive 16B = 512B contiguous). All 8 hoisted up front.
__device__ __forceinline__ void compute_chunk(const char* __restrict__ smW,
                                              uint32_t bbase, int k, int wm,
                                              int wn, int lane,
                                              float d[2][4][4]) {
    int rr = lane & 7, gA = lane >> 3;
    uint4 A[2][2][2];   // [h][mb][kq]
#pragma unroll
    for (int h = 0; h < 2; h++)
#pragma unroll
        for (int mb = 0; mb < 2; mb++)
#pragma unroll
            for (int kq = 0; kq < 2; kq++) {
                int ks = k * 4 + 2 * h + kq;
                A[h][mb][kq] = *reinterpret_cast<const uint4*>(
                    smW + (((2 * wm + mb) * 28 + ks) * 32 + lane) * 16);
            }
#pragma unroll
    for (int h = 0; h < 2; h++) {
#pragma unroll
        for (int tt = 0; tt < 4; tt++) {
            uint32_t addr = bbase + (uint32_t)((wn * 32 + tt * 8 + rr) * 128) +
                            (uint32_t)(((4 * h + gA) ^ rr) << 4);
            uint32_t b0, b1, b2, b3;
            asm volatile(
                "ldmatrix.sync.aligned.m8n8.x4.shared.b16 {%0,%1,%2,%3}, [%4];"
                : "=r"(b0), "=r"(b1), "=r"(b2), "=r"(b3)
                : "r"(addr));
            mma16(d[0][tt], A[h][0][0].x, A[h][0][0].y, A[h][0][0].z,
                  A[h][0][0].w, b0, b1);
            mma16(d[1][tt], A[h][1][0].x, A[h][1][0].y, A[h][1][0].z,
                  A[h][1][0].w, b0, b1);
            mma16(d[0][tt], A[h][0][1].x, A[h][0][1].y, A[h][0][1].z,
                  A[h][0][1].w, b2, b3);
            mma16(d[1][tt], A[h][1][1].x, A[h][1][1].y, A[h][1][1].z,
                  A[h][1][1].w, b2, b3);
        }
    }
}

__global__ __launch_bounds__(256, 2) void fused_kernel(
    const float* __restrict__ bias, float* __restrict__ out) {
    extern __shared__ char sm[];
    char* smW   = sm;                    // W fragment image (57,344 B)
    char* chnk  = sm + OFF_CH;           // 3-chunk ring
    int*  idx_s = (int*)(sm + OFF_IDX);

    int tid  = threadIdx.x;
    int lane = tid & 31;
    int w    = tid >> 5;
    int wm   = w & 1;   // M half (32 output rows)
    int wn   = w >> 1;  // N quarter (32 n-cols)
    int b    = blockIdx.y;
    int n0   = blockIdx.x * TN;
    const __half* xb = g_xh + (size_t)b * Ndim * Cdim;

    for (int e = tid; e < TN * Kn; e += 256) {
        int gi = n0 * Kn + e;
        idx_s[e] = (gi < KN) ? g_idx[gi] : 0;
    }
    __syncthreads();

    // Group 0: W image copy (57,344 B = 3584 16B slots, 14 per thread).
#pragma unroll
    for (int q = 0; q < 14; q++) {
        int e = tid + 256 * q;
        cp16(smW + e * 16, g_wp + e * 4);
    }
    CP_COMMIT();
    // Groups 1,2: first two chunk gathers.
    gather_chunk(xb, idx_s, 0, chnk + 0 * CHUNK_B, tid); CP_COMMIT();
    gather_chunk(xb, idx_s, 1, chnk + 1 * CHUNK_B, tid); CP_COMMIT();

    float d[2][4][4];
#pragma unroll
    for (int i = 0; i < 2; i++)
#pragma unroll
        for (int j = 0; j < 4; j++)
#pragma unroll
            for (int q = 0; q < 4; q++) d[i][j][q] = 0.f;

    uint32_t bb = smem_u32(chnk);

#pragma unroll
    for (int k = 0; k < Kn; k++) {
        // wait_group is positional: N=1 completes everything except the most
        // recently committed group. At k=0 that completes W + chunk0.
        if (k < Kn - 1) asm volatile("cp.async.wait_group 1;\n");
        else            asm volatile("cp.async.wait_group 0;\n");
        // Barrier makes chunk k visible AND proves all warps finished chunk
        // k-1, so ring slot (k+2)%3 == (k-1)%3 is free. One barrier/chunk.
        __syncthreads();
        if (k + 2 < Kn) {
            gather_chunk(xb, idx_s, k + 2, chnk + ((k + 2) % NSTAGE) * CHUNK_B,
                         tid);
            CP_COMMIT();
        }
        compute_chunk(smW, bb + (uint32_t)((k % NSTAGE) * CHUNK_B), k, wm, wn,
                      lane, d);
    }

    // Epilogue: bias + store out[b, o, n] (direct scattered STG — measured
    // faster than smem-staged coalescing in round 14).
#pragma unroll
    for (int mb2 = 0; mb2 < 2; mb2++) {
        int o = wm * 32 + mb2 * 16 + (lane >> 2);
        float bv0 = __ldg(&bias[o]);
        float bv1 = __ldg(&bias[o + 8]);
        float* op0 = out + ((size_t)(b * OUTd + o)) * Ndim;
        float* op1 = op0 + (size_t)8 * Ndim;
#pragma unroll
        for (int tt = 0; tt < 4; tt++) {
            int nb = n0 + wn * 32 + tt * 8 + 2 * (lane & 3);
            if (nb < Ndim) {
                float v0 = d[mb2][tt][0] + bv0;
                float v1 = d[mb2][tt][1] + bv0;
                float v2 = d[mb2][tt][2] + bv1;
                float v3 = d[mb2][tt][3] + bv1;
                if (nb + 1 < Ndim) {
                    *reinterpret_cast<float2*>(op0 + nb) = make_float2(v0, v1);
                    *reinterpret_cast<float2*>(op1 + nb) = make_float2(v2, v3);
                } else {
                    op0[nb] = v0;
                    op1[nb] = v2;
                }
            }
        }
    }
}

// ---------------------------------------------------------------------------
// Launch
// ---------------------------------------------------------------------------
extern "C" void kernel_launch(void* const* d_in, const int* in_sizes, int n_in,
                              void* d_out, int out_size) {
    const float* x     = (const float*)d_in[0];
    const void*  neigh = d_in[1];   // int32 OR int64 (jax x64 trap)
    const float* W     = (const float*)d_in[2];
    const float* bias  = (const float*)d_in[3];
    float*       out   = (float*)d_out;

    cudaFuncSetAttribute(fused_kernel,
                         cudaFuncAttributeMaxDynamicSharedMemorySize,
                         SMEM_BYTES);

    prep_kernel<<<TBLOCKS + WP_BLOCKS + IBLOCKS, 256>>>(x, neigh, W);
    fused_kernel<<<dim3(NTILES, Bdim), 256, SMEM_BYTES>>>(bias, out);
}